// round 7
// baseline (speedup 1.0000x reference)
#include <cuda_runtime.h>
#include <math_constants.h>

// Problem constants: B=32, J=11, C=9, M=N=256
#define BB 32
#define JJ 11
#define CC 9
#define MM 256
#define NN 256
#define HW (MM*NN)                   // 65536 elements per (b,j) map
#define NBOX (BB*JJ)                 // 352
#define BPB 2                        // blocks per box
#define NBLK (NBOX*BPB)              // 704
#define NTHR 256
#define NWARP (NTHR/32)
#define V8_PER_MAP (HW/8)            // 8192 float8 per map
#define V8_PER_SEG (V8_PER_MAP/BPB)  // 4096 per half-map
#define V8_PER_THREAD (V8_PER_SEG/NTHR) // 16

// Device scratch (zero-init at module load; counters self-reset via wrap ->
// graph-replay safe; mailboxes are gated by the counters so stale values are
// never observed).
__device__ unsigned long long g_mail[NBOX][BPB]; // packed (val_bits<<32)|(~idx)
__device__ unsigned int       g_cnt[NBOX];       // per-box arrivals (wrapping)
__device__ float              g_batch[BB];       // per-batch loss accumulator
__device__ unsigned int       g_bcnt[BB];        // per-batch arrivals (wrapping)

// 256-bit read-only load with L2 evict_last (sm_100: hint requires v8.b32).
__device__ __forceinline__ void ldg256_el(const float* p, float v[8]) {
    unsigned r0, r1, r2, r3, r4, r5, r6, r7;
    asm("ld.global.nc.L2::evict_last.v8.b32 {%0,%1,%2,%3,%4,%5,%6,%7}, [%8];"
        : "=r"(r0), "=r"(r1), "=r"(r2), "=r"(r3),
          "=r"(r4), "=r"(r5), "=r"(r6), "=r"(r7)
        : "l"(p));
    v[0] = __uint_as_float(r0); v[1] = __uint_as_float(r1);
    v[2] = __uint_as_float(r2); v[3] = __uint_as_float(r3);
    v[4] = __uint_as_float(r4); v[5] = __uint_as_float(r5);
    v[6] = __uint_as_float(r6); v[7] = __uint_as_float(r7);
}

__global__ __launch_bounds__(NTHR, 6)
void label_loss_fused(const float* __restrict__ pred,
                      const float* __restrict__ gt,
                      const float* __restrict__ heatmap,
                      float* __restrict__ out)
{
    const int blk = blockIdx.x;            // 0..703
    const int box = blk >> 1;              // 0..351
    const int seg = blk & 1;
    const int b   = box / JJ;
    const int t   = threadIdx.x;           // 0..255

    __shared__ float s_val[NWARP];
    __shared__ int   s_idx[NWARP];
    __shared__ float s_gt[11];             // prefetched gt row for this box

    // Prefetch gt row (removes a dependent global load from the tail chain).
    if (t < 11) s_gt[t] = __ldg(&gt[(size_t)box * 11 + t]);

    // ---- streaming argmax over this half-map (256-bit loads) ----
    const float* hm = heatmap + (size_t)box * HW + (size_t)seg * (V8_PER_SEG * 8);

    float best = -CUDART_INF_F;
    int   bidx = 0;                        // map-local flat index (0..65535)

    #pragma unroll 4
    for (int k = 0; k < V8_PER_THREAD; ++k) {
        const int i8 = t + k * NTHR;       // increasing per thread
        float v[8];
        ldg256_el(hm + (size_t)i8 * 8, v);
        const float m01 = fmaxf(v[0], v[1]);
        const float m23 = fmaxf(v[2], v[3]);
        const float m45 = fmaxf(v[4], v[5]);
        const float m67 = fmaxf(v[6], v[7]);
        const float ma  = fmaxf(m01, m23);
        const float mb  = fmaxf(m45, m67);
        const float m8  = fmaxf(ma, mb);
        if (m8 > best) {                   // rare
            best = m8;
            const int base = (seg * V8_PER_SEG + i8) * 8;
            int lane = 7;
            #pragma unroll
            for (int j = 6; j >= 0; --j)
                if (v[j] == m8) lane = j;  // first occurrence wins
            bidx = base + lane;
        }
    }

    // ---- warp reduce (value desc, idx asc tie-break) ----
    #pragma unroll
    for (int off = 16; off > 0; off >>= 1) {
        const float ov = __shfl_down_sync(0xFFFFFFFFu, best, off);
        const int   oi = __shfl_down_sync(0xFFFFFFFFu, bidx, off);
        if (ov > best || (ov == best && oi < bidx)) { best = ov; bidx = oi; }
    }
    if ((t & 31) == 0) { s_val[t >> 5] = best; s_idx[t >> 5] = bidx; }
    __syncthreads();

    // ---- warp 0: shuffle-combine the 8 warp partials ----
    if (t < 32) {
        const int lane = t;
        float v = (lane < NWARP) ? s_val[lane] : -CUDART_INF_F;
        int   i = (lane < NWARP) ? s_idx[lane] : 0x7FFFFFFF;
        #pragma unroll
        for (int off = 4; off > 0; off >>= 1) {
            const float ov = __shfl_down_sync(0xFFFFFFFFu, v, off);
            const int   oi = __shfl_down_sync(0xFFFFFFFFu, i, off);
            if (ov > v || (ov == v && oi < i)) { v = ov; i = oi; }
        }
        if (lane == 0) {
            // Pack: higher value wins; on ties smaller idx wins (~idx larger).
            unsigned long long key =
                ((unsigned long long)__float_as_uint(v) << 32) |
                (unsigned int)(~(unsigned int)i);

            // Mailbox publish + arrival.
            g_mail[box][seg] = key;
            __threadfence();
            const unsigned prev = atomicInc(&g_cnt[box], BPB - 1);
            if (prev == BPB - 1) {
                // Last arrival: read partner's key directly (ordered by its
                // pre-inc threadfence).
                const unsigned long long other =
                    *(volatile unsigned long long*)&g_mail[box][seg ^ 1];
                if (other > key) key = other;

                const float a_xy = __uint_as_float((unsigned int)(key >> 32));
                const int   idx  = (int)(~(unsigned int)key);
                const int x = idx >> 8;    // index // 256
                const int y = idx & 255;   // index % 256

                const float gx = s_gt[9];
                const float gy = s_gt[10];
                const bool valid = (gx >= 0.0f) && (gy >= 0.0f) &&
                                   (gx < (float)MM) && (gy < (float)NN);

                float loss = 0.0f;
                if (valid) {
                    float cls = 0.0f;
                    const size_t pbase = ((size_t)b * CC) * HW
                                       + (size_t)x * NN + (size_t)y;
                    #pragma unroll
                    for (int c = 0; c < CC; ++c) {
                        const float p = __ldg(&pred[pbase + (size_t)c * HW]);
                        const float d = p - s_gt[c];
                        cls = fmaf(d, d, cls);
                    }
                    const float dx = gx - (float)x;
                    const float dy = gy - (float)y;
                    const float ca = 1.0f - a_xy;
                    loss = cls + dx * dx + dy * dy + ca * ca;
                }

                // Per-batch accumulation; last-of-11 finisher writes out[b].
                atomicAdd(&g_batch[b], loss);
                __threadfence();
                const unsigned p2 = atomicInc(&g_bcnt[b], JJ - 1);
                if (p2 == JJ - 1) {
                    // Read-and-reset accumulator -> replay-safe.
                    out[b] = atomicExch(&g_batch[b], 0.0f);
                }
            }
        }
    }
}

extern "C" void kernel_launch(void* const* d_in, const int* in_sizes, int n_in,
                              void* d_out, int out_size)
{
    const float* pred    = (const float*)d_in[0];  // (32, 9, 256, 256)
    const float* gt      = (const float*)d_in[1];  // (32, 11, 11)
    const float* heatmap = (const float*)d_in[2];  // (32, 11, 256, 256)
    float* out = (float*)d_out;                    // (32,)

    label_loss_fused<<<NBLK, NTHR>>>(pred, gt, heatmap, out);
}

// round 8
// speedup vs baseline: 1.0487x; 1.0487x over previous
#include <cuda_runtime.h>
#include <math_constants.h>

// Problem constants: B=32, J=11, C=9, M=N=256
#define BB 32
#define JJ 11
#define CC 9
#define MM 256
#define NN 256
#define HW (MM*NN)                   // 65536 elements per (b,j) map
#define NBOX (BB*JJ)                 // 352
#define NTHR 512
#define NWARP (NTHR/32)              // 16
#define V8_PER_MAP (HW/8)            // 8192 float8 per map
#define V8_PER_THREAD (V8_PER_MAP/NTHR) // 16

// Device scratch (zero-init at module load; counter wraps and accumulator is
// read-and-reset -> graph-replay safe).
__device__ float        g_batch[BB];   // per-batch loss accumulator
__device__ unsigned int g_bcnt[BB];    // per-batch arrivals (wrapping)

// 256-bit read-only load with L2 evict_last (sm_100: hint requires v8.b32).
__device__ __forceinline__ void ldg256_el(const float* p, float v[8]) {
    unsigned r0, r1, r2, r3, r4, r5, r6, r7;
    asm("ld.global.nc.L2::evict_last.v8.b32 {%0,%1,%2,%3,%4,%5,%6,%7}, [%8];"
        : "=r"(r0), "=r"(r1), "=r"(r2), "=r"(r3),
          "=r"(r4), "=r"(r5), "=r"(r6), "=r"(r7)
        : "l"(p));
    v[0] = __uint_as_float(r0); v[1] = __uint_as_float(r1);
    v[2] = __uint_as_float(r2); v[3] = __uint_as_float(r3);
    v[4] = __uint_as_float(r4); v[5] = __uint_as_float(r5);
    v[6] = __uint_as_float(r6); v[7] = __uint_as_float(r7);
}

__global__ __launch_bounds__(NTHR, 3)
void label_loss_fused(const float* __restrict__ pred,
                      const float* __restrict__ gt,
                      const float* __restrict__ heatmap,
                      float* __restrict__ out)
{
    const int box = blockIdx.x;            // 0..351 (one CTA owns one box)
    const int b   = box / JJ;
    const int t   = threadIdx.x;           // 0..511

    __shared__ float s_val[NWARP];
    __shared__ int   s_idx[NWARP];
    __shared__ float s_gt[11];

    // Prefetch gt row; hides the dependent load from the tail chain.
    if (t < 11) s_gt[t] = __ldg(&gt[(size_t)box * 11 + t]);

    // ---- streaming argmax over the whole map (256-bit loads) ----
    const float* hm = heatmap + (size_t)box * HW;

    float best = -CUDART_INF_F;
    int   bidx = 0;                        // flat index (0..65535)

    #pragma unroll 4
    for (int k = 0; k < V8_PER_THREAD; ++k) {
        const int i8 = t + k * NTHR;       // increasing per thread
        float v[8];
        ldg256_el(hm + (size_t)i8 * 8, v);
        const float m01 = fmaxf(v[0], v[1]);
        const float m23 = fmaxf(v[2], v[3]);
        const float m45 = fmaxf(v[4], v[5]);
        const float m67 = fmaxf(v[6], v[7]);
        const float ma  = fmaxf(m01, m23);
        const float mb  = fmaxf(m45, m67);
        const float m8  = fmaxf(ma, mb);
        if (m8 > best) {                   // rare
            best = m8;
            int lane = 7;
            #pragma unroll
            for (int j = 6; j >= 0; --j)
                if (v[j] == m8) lane = j;  // first occurrence wins
            bidx = i8 * 8 + lane;
        }
    }

    // ---- warp reduce (value desc, idx asc tie-break) ----
    #pragma unroll
    for (int off = 16; off > 0; off >>= 1) {
        const float ov = __shfl_down_sync(0xFFFFFFFFu, best, off);
        const int   oi = __shfl_down_sync(0xFFFFFFFFu, bidx, off);
        if (ov > best || (ov == best && oi < bidx)) { best = ov; bidx = oi; }
    }
    if ((t & 31) == 0) { s_val[t >> 5] = best; s_idx[t >> 5] = bidx; }
    __syncthreads();

    // ---- warp 0: shuffle-combine the 16 warp partials, then finish ----
    if (t < 32) {
        float v = (t < NWARP) ? s_val[t] : -CUDART_INF_F;
        int   i = (t < NWARP) ? s_idx[t] : 0x7FFFFFFF;
        #pragma unroll
        for (int off = 8; off > 0; off >>= 1) {
            const float ov = __shfl_down_sync(0xFFFFFFFFu, v, off);
            const int   oi = __shfl_down_sync(0xFFFFFFFFu, i, off);
            if (ov > v || (ov == v && oi < i)) { v = ov; i = oi; }
        }
        if (t == 0) {
            const float a_xy = v;
            const int x = i >> 8;          // index // 256
            const int y = i & 255;         // index % 256

            const float gx = s_gt[9];
            const float gy = s_gt[10];
            const bool valid = (gx >= 0.0f) && (gy >= 0.0f) &&
                               (gx < (float)MM) && (gy < (float)NN);

            float loss = 0.0f;
            if (valid) {
                float cls = 0.0f;
                const size_t pbase = ((size_t)b * CC) * HW
                                   + (size_t)x * NN + (size_t)y;
                #pragma unroll
                for (int c = 0; c < CC; ++c) {
                    const float p = __ldg(&pred[pbase + (size_t)c * HW]);
                    const float d = p - s_gt[c];
                    cls = fmaf(d, d, cls);
                }
                const float dx = gx - (float)x;
                const float dy = gy - (float)y;
                const float ca = 1.0f - a_xy;
                loss = cls + dx * dx + dy * dy + ca * ca;
            }

            // Per-batch accumulation; last-of-11 finisher writes out[b].
            atomicAdd(&g_batch[b], loss);
            __threadfence();
            const unsigned p2 = atomicInc(&g_bcnt[b], JJ - 1);
            if (p2 == JJ - 1) {
                // Read-and-reset accumulator -> replay-safe.
                out[b] = atomicExch(&g_batch[b], 0.0f);
            }
        }
    }
}

extern "C" void kernel_launch(void* const* d_in, const int* in_sizes, int n_in,
                              void* d_out, int out_size)
{
    const float* pred    = (const float*)d_in[0];  // (32, 9, 256, 256)
    const float* gt      = (const float*)d_in[1];  // (32, 11, 11)
    const float* heatmap = (const float*)d_in[2];  // (32, 11, 256, 256)
    float* out = (float*)d_out;                    // (32,)

    label_loss_fused<<<NBOX, NTHR>>>(pred, gt, heatmap, out);
}